// round 3
// baseline (speedup 1.0000x reference)
#include <cuda_runtime.h>

#define TI 16
#define TJ 128
#define NT 256
#define LSEQ 2048
#define DK 64
#define NH 8
#define NB 2
#define KTPAD 132   // TJ + 4: breaks bank-conflict stride, keeps float4 alignment

#define MASK_ELEMS ((size_t)NB * LSEQ * LSEQ)

// smem layout (floats):
//  sS   : TI*LSEQ              = 32768
//  sAux : max(64*KTPAD, TJ*DK) =  8448   (K^T staging, then V staging)
//  sQ   : TI*DK                =  1024
//  sRow : TI                   =    16   (1/rowsum)
#define SMEM_FLOATS (TI*LSEQ + 64*KTPAD + TI*DK + TI)
#define SMEM_BYTES  (SMEM_FLOATS * sizeof(float))

// Scratch: normalized mask (1 byte per logical element) + dtype flag.
__device__ unsigned char g_mask[MASK_ELEMS];
__device__ int g_flag;

// ---------------------------------------------------------------------------
// Mask dtype detection: sample 4096 leading elements.
//   float32 {0.0,1.0} data: int view = 0x3F800000 -> not in {0,1}
//   int32   {0,1}     data: float view of 1 = denormal -> not in {0.0,1.0}
//   bool bytes: both views are garbage -> neither passes
// flag: 0 = bool(1B), 1 = int32, 2 = float32
// ---------------------------------------------------------------------------
__global__ void detect_kernel(const unsigned char* __restrict__ m)
{
    __shared__ int isF, isI;
    if (threadIdx.x == 0) { isF = 1; isI = 1; }
    __syncthreads();
    const float* f = (const float*)m;
    const int*   ii = (const int*)m;
    for (int i = threadIdx.x; i < 4096; i += blockDim.x) {
        float fv = f[i];
        if (!(fv == 0.0f || fv == 1.0f)) atomicAnd(&isF, 0);
        int iv = ii[i];
        if (!(iv == 0 || iv == 1))       atomicAnd(&isI, 0);
    }
    __syncthreads();
    if (threadIdx.x == 0) g_flag = isF ? 2 : (isI ? 1 : 0);
}

__global__ void convert_kernel(const unsigned char* __restrict__ m)
{
    const int flag = g_flag;
    size_t i0 = ((size_t)blockIdx.x * blockDim.x + threadIdx.x) * 4;
    if (i0 >= MASK_ELEMS) return;
    uchar4 o;
    if (flag == 0) {
        o = *(const uchar4*)(m + i0);
        o.x = o.x ? 1 : 0; o.y = o.y ? 1 : 0; o.z = o.z ? 1 : 0; o.w = o.w ? 1 : 0;
    } else if (flag == 1) {
        int4 v = *(const int4*)((const int*)m + i0);
        o.x = v.x != 0; o.y = v.y != 0; o.z = v.z != 0; o.w = v.w != 0;
    } else {
        float4 v = *(const float4*)((const float*)m + i0);
        o.x = v.x != 0.f; o.y = v.y != 0.f; o.z = v.z != 0.f; o.w = v.w != 0.f;
    }
    *(uchar4*)(g_mask + i0) = o;
}

// ---------------------------------------------------------------------------
// Main fused attention kernel (one CTA per (b,h, 16-row query tile))
// ---------------------------------------------------------------------------
__global__ __launch_bounds__(NT, 1)
void raa_kernel(const float* __restrict__ Q, const float* __restrict__ K,
                const float* __restrict__ V,
                const float* __restrict__ TS, const float* __restrict__ LS,
                float* __restrict__ Osum, float* __restrict__ Pout)
{
    extern __shared__ float sm[];
    float* sS   = sm;                    // [TI][LSEQ]
    float* sAux = sS + TI * LSEQ;        // K^T: [DK][KTPAD]  /  V: [TJ][DK]
    float* sQ   = sAux + 64 * KTPAD;     // [TI][DK]
    float* sRow = sQ + TI * DK;          // [TI]

    const int t  = threadIdx.x;
    const int bh = blockIdx.y;
    const int b  = bh >> 3;              // H = 8
    const int i0 = blockIdx.x * TI;
    const float scale = 0.07216878364870323f;   // 1/sqrt(3*64)

    const float* Qb  = Q  + (size_t)bh * LSEQ * DK;
    const float* Kb  = K  + (size_t)bh * LSEQ * DK;
    const float* Vb  = V  + (size_t)bh * LSEQ * DK;
    const float* TSb = TS + ((size_t)bh * LSEQ + i0) * LSEQ;
    const float* LSb = LS + ((size_t)bh * LSEQ + i0) * LSEQ;
    const unsigned char* Mb = g_mask + ((size_t)b * LSEQ + i0) * LSEQ;

    // ---- load Q tile (TI*DK = 1024 floats = 256 float4, one per thread) ----
    {
        const float4* q4 = (const float4*)(Qb + (size_t)i0 * DK);
        ((float4*)sQ)[t] = q4[t];
    }

    // ---- Phase 1: S = (Q K^T + tree + leaf) * scale, masked ----
    const int jq = t & 31;        // j quad: columns 4*jq .. 4*jq+3
    const int ip = t >> 5;        // i pair
    const int ra = 2 * ip, rb = 2 * ip + 1;

    for (int jc = 0; jc < LSEQ; jc += TJ) {
        __syncthreads();   // sAux free (Q-load done / previous chunk consumed)
        // stage K chunk transposed: sAux[kk][j], 2048 float4 loads
        #pragma unroll
        for (int it = 0; it < 8; it++) {
            int idx = t + it * NT;          // 0..2047
            int j   = idx >> 4;             // 0..127
            int kk0 = (idx & 15) << 2;      // 0,4,..,60
            float4 kv = *(const float4*)(Kb + (size_t)(jc + j) * DK + kk0);
            sAux[(kk0 + 0) * KTPAD + j] = kv.x;
            sAux[(kk0 + 1) * KTPAD + j] = kv.y;
            sAux[(kk0 + 2) * KTPAD + j] = kv.z;
            sAux[(kk0 + 3) * KTPAD + j] = kv.w;
        }
        __syncthreads();

        float4 a0 = {0.f,0.f,0.f,0.f}, a1 = {0.f,0.f,0.f,0.f};
        #pragma unroll 16
        for (int kk = 0; kk < DK; kk++) {
            float4 kv = *(const float4*)(sAux + kk * KTPAD + 4 * jq);
            float qa = sQ[ra * DK + kk];
            float qb = sQ[rb * DK + kk];
            a0.x = fmaf(qa, kv.x, a0.x); a0.y = fmaf(qa, kv.y, a0.y);
            a0.z = fmaf(qa, kv.z, a0.z); a0.w = fmaf(qa, kv.w, a0.w);
            a1.x = fmaf(qb, kv.x, a1.x); a1.y = fmaf(qb, kv.y, a1.y);
            a1.z = fmaf(qb, kv.z, a1.z); a1.w = fmaf(qb, kv.w, a1.w);
        }

        const int jg = jc + 4 * jq;
        {
            float4 t4 = *(const float4*)(TSb + (size_t)ra * LSEQ + jg);
            float4 l4 = *(const float4*)(LSb + (size_t)ra * LSEQ + jg);
            uchar4 m4 = *(const uchar4*)(Mb + (size_t)ra * LSEQ + jg);
            float4 s;
            s.x = m4.x ? -1e9f : (a0.x + t4.x + l4.x) * scale;
            s.y = m4.y ? -1e9f : (a0.y + t4.y + l4.y) * scale;
            s.z = m4.z ? -1e9f : (a0.z + t4.z + l4.z) * scale;
            s.w = m4.w ? -1e9f : (a0.w + t4.w + l4.w) * scale;
            *(float4*)(sS + ra * LSEQ + jg) = s;
        }
        {
            float4 t4 = *(const float4*)(TSb + (size_t)rb * LSEQ + jg);
            float4 l4 = *(const float4*)(LSb + (size_t)rb * LSEQ + jg);
            uchar4 m4 = *(const uchar4*)(Mb + (size_t)rb * LSEQ + jg);
            float4 s;
            s.x = m4.x ? -1e9f : (a1.x + t4.x + l4.x) * scale;
            s.y = m4.y ? -1e9f : (a1.y + t4.y + l4.y) * scale;
            s.z = m4.z ? -1e9f : (a1.z + t4.z + l4.z) * scale;
            s.w = m4.w ? -1e9f : (a1.w + t4.w + l4.w) * scale;
            *(float4*)(sS + rb * LSEQ + jg) = s;
        }
    }
    __syncthreads();

    // ---- Phase 2: per-row max / exp / sum (16 threads per row) ----
    {
        const int row = t >> 4;
        const int l16 = t & 15;
        float* sSr = sS + row * LSEQ;
        float m = -3.4e38f;
        for (int j = l16; j < LSEQ; j += 16) m = fmaxf(m, sSr[j]);
        #pragma unroll
        for (int k = 8; k >= 1; k >>= 1)
            m = fmaxf(m, __shfl_xor_sync(0xffffffffu, m, k));
        float sum = 0.f;
        for (int j = l16; j < LSEQ; j += 16) {
            float e = __expf(sSr[j] - m);
            sSr[j] = e;
            sum += e;
        }
        #pragma unroll
        for (int k = 8; k >= 1; k >>= 1)
            sum += __shfl_xor_sync(0xffffffffu, sum, k);
        if (l16 == 0) sRow[row] = 1.0f / sum;
    }
    __syncthreads();

    // ---- Phase 3: normalize in smem + stream p_attn to gmem ----
    {
        float* Pb = Pout + ((size_t)bh * LSEQ + i0) * LSEQ;
        #pragma unroll
        for (int it = 0; it < (TI * LSEQ / 4) / NT; it++) {   // 32 iters
            int fidx = (t + it * NT) * 4;
            int r = fidx >> 11;                                // /LSEQ
            float rinv = sRow[r];
            float4 p = *(float4*)(sS + fidx);
            p.x *= rinv; p.y *= rinv; p.z *= rinv; p.w *= rinv;
            *(float4*)(sS + fidx) = p;
            *(float4*)(Pb + fidx) = p;
        }
    }

    // ---- Phase 4: O = P V ----
    const int oi = t >> 4;            // output row 0..15
    const int od = (t & 15) << 2;     // output cols od..od+3
    float4 acc = {0.f,0.f,0.f,0.f};
    for (int jc = 0; jc < LSEQ; jc += TJ) {
        __syncthreads();  // orders phase-3 sS stores before reads; sAux free
        #pragma unroll
        for (int it = 0; it < 8; it++) {
            int idx = t + it * NT;    // 0..2047 float4s of the V chunk
            *(float4*)(sAux + idx * 4) =
                *(const float4*)(Vb + (size_t)jc * DK + idx * 4);
        }
        __syncthreads();
        const float* pr = sS + oi * LSEQ + jc;
        #pragma unroll 4
        for (int jj = 0; jj < TJ; jj++) {
            float p = pr[jj];
            float4 v = *(const float4*)(sAux + jj * DK + od);
            acc.x = fmaf(p, v.x, acc.x);
            acc.y = fmaf(p, v.y, acc.y);
            acc.z = fmaf(p, v.z, acc.z);
            acc.w = fmaf(p, v.w, acc.w);
        }
    }
    *(float4*)(Osum + ((size_t)bh * LSEQ + i0 + oi) * DK + od) = acc;
}

extern "C" void kernel_launch(void* const* d_in, const int* in_sizes, int n_in,
                              void* d_out, int out_size)
{
    const float* Q  = (const float*)d_in[0];
    const float* K  = (const float*)d_in[1];
    const float* V  = (const float*)d_in[2];
    const unsigned char* M = (const unsigned char*)d_in[3];
    const float* TS = (const float*)d_in[4];
    const float* LS = (const float*)d_in[5];

    float* out  = (float*)d_out;
    float* Osum = out;                                    // (B,H,L,DK)
    float* Pout = out + (size_t)NB * NH * LSEQ * DK;      // (B,H,L,L)

    detect_kernel<<<1, 256>>>(M);
    convert_kernel<<<(int)(MASK_ELEMS / 4 / 256), 256>>>(M);

    cudaFuncSetAttribute(raa_kernel,
                         cudaFuncAttributeMaxDynamicSharedMemorySize,
                         (int)SMEM_BYTES);

    dim3 grid(LSEQ / TI, NB * NH);
    raa_kernel<<<grid, NT, SMEM_BYTES>>>(Q, K, V, TS, LS, Osum, Pout);
}